// round 2
// baseline (speedup 1.0000x reference)
#include <cuda_runtime.h>

#define NN 10000
#define EE 40000
#define FIN 30
#define FE 11
#define EMB 64
#define BB 128
#define HC 17           // 16 hidden channels + 1 folded-bias channel
#define ZC (HC * EMB)   // 1088

// ---------------- device scratch (static globals — no allocation) ----------------
__device__ float g_h0[EE * HC];      // layer-0 edge MLP output (+1 channel)
__device__ float g_h1[EE * HC];      // layer-1/2 edge MLP output (shared weights)
__device__ float g_Wr0[FIN * ZC];    // rearranged w2 for layer 0: [in, 17*64]
__device__ float g_Wr1[EMB * ZC];    // rearranged w2 for layers 1-2
__device__ float g_z[NN * ZC];       // per-node factorized tensor [N, 17*64]
__device__ float g_bufA[NN * EMB];
__device__ float g_bufB[NN * EMB];
__device__ float g_agg[NN * EMB];
__device__ float g_pool[BB * EMB];
__device__ float g_v[EMB + 1];       // collapsed head vector + scalar

// ---------------- kernels ----------------

__global__ void zero_kernel(float* p, int n) {
    for (int i = blockIdx.x * blockDim.x + threadIdx.x; i < n; i += gridDim.x * blockDim.x)
        p[i] = 0.f;
}

// h = relu(edge_attr @ w1 + b1), with trailing 1.0 channel. Two weight sets at once.
__global__ void edge_mlp_kernel(const float* __restrict__ ea,
                                const float* __restrict__ w1a, const float* __restrict__ b1a,
                                const float* __restrict__ w1b, const float* __restrict__ b1b) {
    __shared__ float swa[FE * 16], swb[FE * 16], sba[16], sbb[16];
    int tid = threadIdx.x;
    for (int t = tid; t < FE * 16; t += blockDim.x) { swa[t] = w1a[t]; swb[t] = w1b[t]; }
    if (tid < 16) { sba[tid] = b1a[tid]; sbb[tid] = b1b[tid]; }
    __syncthreads();
    int e = blockIdx.x * blockDim.x + tid;
    if (e >= EE) return;
    float a[FE];
#pragma unroll
    for (int i = 0; i < FE; i++) a[i] = ea[e * FE + i];
#pragma unroll
    for (int j = 0; j < 16; j++) {
        float s = sba[j], s2 = sbb[j];
#pragma unroll
        for (int i = 0; i < FE; i++) { s += a[i] * swa[i * 16 + j]; s2 += a[i] * swb[i * 16 + j]; }
        g_h0[e * HC + j] = fmaxf(s, 0.f);
        g_h1[e * HC + j] = fmaxf(s2, 0.f);
    }
    g_h0[e * HC + 16] = 1.f;
    g_h1[e * HC + 16] = 1.f;
}

// Wr[i, k*64+o] = w2[k, i*64+o] for k<16 ; Wr[i, 16*64+o] = b2[i*64+o]
__global__ void build_wr_kernel(const float* __restrict__ w2, const float* __restrict__ b2,
                                float* __restrict__ Wr, int in_dim) {
    int idx = blockIdx.x * blockDim.x + threadIdx.x;
    int total = in_dim * ZC;
    if (idx >= total) return;
    int i = idx / ZC;
    int r = idx - i * ZC;
    int k = r >> 6;
    int o = r & 63;
    Wr[idx] = (k < 16) ? w2[k * (in_dim * EMB) + i * EMB + o] : b2[i * EMB + o];
}

// C[M x 1088] = A[M x K] @ B[K x 1088].  64x64 tile, 256 threads, 4x4 microtile.
#define GK 32
__global__ __launch_bounds__(256) void gemm_kernel(const float* __restrict__ A,
                                                   const float* __restrict__ B,
                                                   float* __restrict__ C, int M, int K) {
    __shared__ float As[GK][64 + 1];
    __shared__ float Bs[GK][64 + 1];
    int tid = threadIdx.x;
    int tx = tid & 15, ty = tid >> 4;
    int m0 = blockIdx.y * 64, n0 = blockIdx.x * 64;
    float acc[4][4] = {};
    for (int kb = 0; kb < K; kb += GK) {
        for (int t = tid; t < 64 * GK; t += 256) {
            int m = t / GK, k = t - m * GK;
            int gm = m0 + m, gk = kb + k;
            As[k][m] = (gm < M && gk < K) ? A[(size_t)gm * K + gk] : 0.f;
        }
        for (int t = tid; t < GK * 64; t += 256) {
            int k = t >> 6, n = t & 63;
            int gk = kb + k;
            Bs[k][n] = (gk < K) ? B[(size_t)gk * ZC + n0 + n] : 0.f;
        }
        __syncthreads();
#pragma unroll
        for (int k = 0; k < GK; k++) {
            float ra[4], rb[4];
#pragma unroll
            for (int i = 0; i < 4; i++) ra[i] = As[k][ty * 4 + i];
#pragma unroll
            for (int j = 0; j < 4; j++) rb[j] = Bs[k][tx * 4 + j];
#pragma unroll
            for (int i = 0; i < 4; i++)
#pragma unroll
                for (int j = 0; j < 4; j++) acc[i][j] += ra[i] * rb[j];
        }
        __syncthreads();
    }
#pragma unroll
    for (int i = 0; i < 4; i++) {
        int gm = m0 + ty * 4 + i;
        if (gm < M)
#pragma unroll
            for (int j = 0; j < 4; j++) C[(size_t)gm * ZC + n0 + tx * 4 + j] = acc[i][j];
    }
}

// Per edge: msg[o] = sum_k h'[k] * z[src][k*64+o]; atomicAdd into agg[dst].
__global__ __launch_bounds__(256) void edge_agg_kernel(const int* __restrict__ ei,
                                                       const float* __restrict__ h,
                                                       const float* __restrict__ z,
                                                       float* __restrict__ agg) {
    int e = blockIdx.x * 8 + (threadIdx.x >> 5);
    if (e >= EE) return;
    int lane = threadIdx.x & 31;
    int src = ei[e];
    int dst = ei[EE + e];
    const float* zr = z + (size_t)src * ZC;
    float hv = (lane < HC) ? h[e * HC + lane] : 0.f;
    float m0 = 0.f, m1 = 0.f;
#pragma unroll
    for (int k = 0; k < HC; k++) {
        float hk = __shfl_sync(0xFFFFFFFFu, hv, k);
        m0 += hk * zr[k * 64 + lane];
        m1 += hk * zr[k * 64 + 32 + lane];
    }
    atomicAdd(&agg[dst * EMB + lane], m0);
    atomicAdd(&agg[dst * EMB + 32 + lane], m1);
}

// out = relu(agg + xin @ root + bias).  256 threads = 4 nodes x 64 outputs.
__global__ __launch_bounds__(256) void root_relu_kernel(const float* __restrict__ agg,
                                                        const float* __restrict__ xin,
                                                        const float* __restrict__ root,
                                                        const float* __restrict__ bias,
                                                        float* __restrict__ out, int in_dim) {
    __shared__ float sroot[EMB * EMB];
    __shared__ float sbias[EMB];
    int tid = threadIdx.x;
    for (int t = tid; t < in_dim * EMB; t += 256) sroot[t] = root[t];
    if (tid < EMB) sbias[tid] = bias[tid];
    __syncthreads();
    int node = blockIdx.x * 4 + (tid >> 6);
    int o = tid & 63;
    if (node >= NN) return;
    float s = agg[node * EMB + o] + sbias[o];
    const float* xr = xin + (size_t)node * in_dim;
    for (int i = 0; i < in_dim; i++) s += xr[i] * sroot[i * EMB + o];
    out[node * EMB + o] = fmaxf(s, 0.f);
}

// segment_max over sorted batch assignment; binary search for graph boundaries.
__global__ void pool_kernel(const float* __restrict__ h, const int* __restrict__ batch) {
    int b = blockIdx.x, o = threadIdx.x;
    __shared__ int sb[2];
    if (o < 2) {
        int target = b + o, lo = 0, hi = NN;
        while (lo < hi) { int mid = (lo + hi) >> 1; if (batch[mid] < target) lo = mid + 1; else hi = mid; }
        sb[o] = lo;
    }
    __syncthreads();
    float m = -3.402823466e38f;
    for (int n = sb[0]; n < sb[1]; n++) m = fmaxf(m, h[(size_t)n * EMB + o]);
    g_pool[b * EMB + o] = m;
}

// v = lin0_w @ lin1_w ; c = lin0_b . lin1_w + lin1_b
__global__ void head_v_kernel(const float* __restrict__ l0w, const float* __restrict__ l0b,
                              const float* __restrict__ l1w, const float* __restrict__ l1b) {
    int i = threadIdx.x;
    float s = 0.f;
    for (int j = 0; j < EMB; j++) s += l0w[i * EMB + j] * l1w[j];
    g_v[i] = s;
    if (i == 0) {
        float c = l1b[0];
        for (int j = 0; j < EMB; j++) c += l0b[j] * l1w[j];
        g_v[EMB] = c;
    }
}

__global__ void head_out_kernel(float* __restrict__ out) {
    int b = blockIdx.x, t = threadIdx.x;
    __shared__ float red[EMB];
    red[t] = g_pool[b * EMB + t] * g_v[t];
    __syncthreads();
    for (int s = 32; s > 0; s >>= 1) {
        if (t < s) red[t] += red[t + s];
        __syncthreads();
    }
    if (t == 0) out[b] = red[0] + g_v[EMB];
}

// ---------------- launch ----------------
extern "C" void kernel_launch(void* const* d_in, const int* in_sizes, int n_in,
                              void* d_out, int out_size) {
    const float* x     = (const float*)d_in[0];
    const float* ea    = (const float*)d_in[1];
    const int*   ei    = (const int*)d_in[2];
    const int*   batch = (const int*)d_in[3];
    const float* ew0_1 = (const float*)d_in[4];
    const float* eb0_1 = (const float*)d_in[5];
    const float* ew0_2 = (const float*)d_in[6];
    const float* eb0_2 = (const float*)d_in[7];
    const float* ew1_1 = (const float*)d_in[8];
    const float* eb1_1 = (const float*)d_in[9];
    const float* ew1_2 = (const float*)d_in[10];
    const float* eb1_2 = (const float*)d_in[11];
    const float* root0 = (const float*)d_in[12];
    const float* bias0 = (const float*)d_in[13];
    const float* root1 = (const float*)d_in[14];
    const float* bias1 = (const float*)d_in[15];
    const float* root2 = (const float*)d_in[16];
    const float* bias2 = (const float*)d_in[17];
    const float* l0w   = (const float*)d_in[18];
    const float* l0b   = (const float*)d_in[19];
    const float* l1w   = (const float*)d_in[20];
    const float* l1b   = (const float*)d_in[21];
    float* out = (float*)d_out;

    float *h0p, *h1p, *Wr0p, *Wr1p, *zp, *bufAp, *bufBp, *aggp;
    cudaGetSymbolAddress((void**)&h0p,   g_h0);
    cudaGetSymbolAddress((void**)&h1p,   g_h1);
    cudaGetSymbolAddress((void**)&Wr0p,  g_Wr0);
    cudaGetSymbolAddress((void**)&Wr1p,  g_Wr1);
    cudaGetSymbolAddress((void**)&zp,    g_z);
    cudaGetSymbolAddress((void**)&bufAp, g_bufA);
    cudaGetSymbolAddress((void**)&bufBp, g_bufB);
    cudaGetSymbolAddress((void**)&aggp,  g_agg);

    dim3 gemm_grid(ZC / 64, (NN + 63) / 64);

    edge_mlp_kernel<<<(EE + 255) / 256, 256>>>(ea, ew0_1, eb0_1, ew1_1, eb1_1);
    build_wr_kernel<<<(FIN * ZC + 255) / 256, 256>>>(ew0_2, eb0_2, Wr0p, FIN);
    build_wr_kernel<<<(EMB * ZC + 255) / 256, 256>>>(ew1_2, eb1_2, Wr1p, EMB);

    // layer 0
    gemm_kernel<<<gemm_grid, 256>>>(x, Wr0p, zp, NN, FIN);
    zero_kernel<<<256, 256>>>(aggp, NN * EMB);
    edge_agg_kernel<<<(EE + 7) / 8, 256>>>(ei, h0p, zp, aggp);
    root_relu_kernel<<<(NN + 3) / 4, 256>>>(aggp, x, root0, bias0, bufAp, FIN);

    // layer 1
    gemm_kernel<<<gemm_grid, 256>>>(bufAp, Wr1p, zp, NN, EMB);
    zero_kernel<<<256, 256>>>(aggp, NN * EMB);
    edge_agg_kernel<<<(EE + 7) / 8, 256>>>(ei, h1p, zp, aggp);
    root_relu_kernel<<<(NN + 3) / 4, 256>>>(aggp, bufAp, root1, bias1, bufBp, EMB);

    // layer 2 (shared edge-MLP weights -> reuse Wr1 and h1)
    gemm_kernel<<<gemm_grid, 256>>>(bufBp, Wr1p, zp, NN, EMB);
    zero_kernel<<<256, 256>>>(aggp, NN * EMB);
    edge_agg_kernel<<<(EE + 7) / 8, 256>>>(ei, h1p, zp, aggp);
    root_relu_kernel<<<(NN + 3) / 4, 256>>>(aggp, bufBp, root2, bias2, bufAp, EMB);

    // pool + head
    pool_kernel<<<BB, EMB>>>(bufAp, batch);
    head_v_kernel<<<1, EMB>>>(l0w, l0b, l1w, l1b);
    head_out_kernel<<<BB, EMB>>>(out);
}